// round 5
// baseline (speedup 1.0000x reference)
#include <cuda_runtime.h>
#include <cstdint>

#define HID 256
#define H4  64            // HID/4 float4 per row
#define NB  1024          // number of graphs
#define EPS 1e-5f

// scratch (allocation-free rule: static __device__ globals)
__device__ float g_hpool[NB * HID];
__device__ float g_h1[NB * HID];
__device__ float g_sum[HID];
__device__ float g_sumsq[HID];
__device__ int   g_segstart[NB + 1];

// ---------------------------------------------------------------------------
// 0) segment bounds: parallel binary search, one thread per graph.
//    Also zeroes the BN stat accumulators.
// ---------------------------------------------------------------------------
__global__ __launch_bounds__(256) void bounds_kernel(
    const int* __restrict__ bidx, int* __restrict__ segstart,
    float* __restrict__ gsum, float* __restrict__ gsumsq, int n)
{
    int b = blockIdx.x * 256 + threadIdx.x;
    if (blockIdx.x == 0) { gsum[threadIdx.x] = 0.f; gsumsq[threadIdx.x] = 0.f; }
    if (b > NB) return;
    if (b == NB) { segstart[NB] = n; return; }
    int lo = 0, hi = n;
    while (lo < hi) { int m = (lo + hi) >> 1; if (__ldg(&bidx[m]) < b) lo = m + 1; else hi = m; }
    segstart[b] = lo;
}

// ---------------------------------------------------------------------------
// 1) segment-sum pooling (+ virtual_node). Bounds precomputed -> stream
//    immediately. 2 blocks per graph (column halves), 32 f4 cols x 8 rowgrps.
//    Manual ILP-2: two independent loads in flight per iteration.
// ---------------------------------------------------------------------------
__global__ __launch_bounds__(256) void pool_kernel(
    const float* __restrict__ x, const int* __restrict__ segstart,
    const float* __restrict__ vnode, float* __restrict__ hpool)
{
    int t    = threadIdx.x;
    int b    = blockIdx.x >> 1;
    int half = blockIdx.x & 1;

    int seg_lo = __ldg(&segstart[b]);
    int seg_hi = __ldg(&segstart[b + 1]);

    int c4 = (half << 5) + (t & 31);   // global float4 column 0..63
    int rg = t >> 5;                   // row group 0..7

    const float4* x4 = reinterpret_cast<const float4*>(x);
    float4 acc0 = make_float4(0.f, 0.f, 0.f, 0.f);
    float4 acc1 = make_float4(0.f, 0.f, 0.f, 0.f);

    int r = seg_lo + rg;
    for (; r + 8 < seg_hi; r += 16) {
        float4 v0 = __ldcs(&x4[(size_t)r * H4 + c4]);
        float4 v1 = __ldcs(&x4[(size_t)(r + 8) * H4 + c4]);
        acc0.x += v0.x; acc0.y += v0.y; acc0.z += v0.z; acc0.w += v0.w;
        acc1.x += v1.x; acc1.y += v1.y; acc1.z += v1.z; acc1.w += v1.w;
    }
    if (r < seg_hi) {
        float4 v0 = __ldcs(&x4[(size_t)r * H4 + c4]);
        acc0.x += v0.x; acc0.y += v0.y; acc0.z += v0.z; acc0.w += v0.w;
    }
    acc0.x += acc1.x; acc0.y += acc1.y; acc0.z += acc1.z; acc0.w += acc1.w;

    __shared__ float4 sm[256];
    sm[t] = acc0;
    __syncthreads();
    if (t < 32) {
        float4 o = reinterpret_cast<const float4*>(vnode)[b * H4 + c4];
#pragma unroll
        for (int g = 0; g < 8; g++) {
            float4 v = sm[g * 32 + t];
            o.x += v.x; o.y += v.y; o.z += v.z; o.w += v.w;
        }
        reinterpret_cast<float4*>(hpool)[b * H4 + c4] = o;
    }
}

// ---------------------------------------------------------------------------
// 2) GEMM1: h1 = hpool @ W1 + b1, fused BN-stat partial sums (atomicAdd).
//    16x64 tile, K-chunk 32, 256 thr, 1x4 micro-tile. grid (4,64)=256 blocks.
// ---------------------------------------------------------------------------
__global__ __launch_bounds__(256) void gemm1_kernel(
    const float* __restrict__ A, const float* __restrict__ W,
    const float* __restrict__ bias, float* __restrict__ C,
    float* __restrict__ gsum, float* __restrict__ gsumsq)
{
    __shared__ float  As[16][33];
    __shared__ float4 Bs4[32][16];
    __shared__ float  red_s[16][64];
    __shared__ float  red_q[16][64];

    int t  = threadIdx.x;
    int tx = t & 15, ty = t >> 4;
    int m0 = blockIdx.y * 16;
    int n0 = blockIdx.x * 64;

    float acc[4] = {0.f, 0.f, 0.f, 0.f};

    int brow = t >> 4, bq = t & 15;    // B: 16 rows x 16 float4 (x2)

    for (int k0 = 0; k0 < HID; k0 += 32) {
        if (t < 128) {
            int arow = t >> 3, aq = t & 7;   // A: 16 rows x 8 float4
            float4 av = *reinterpret_cast<const float4*>(&A[(size_t)(m0 + arow) * HID + k0 + aq * 4]);
            As[arow][aq * 4 + 0] = av.x;
            As[arow][aq * 4 + 1] = av.y;
            As[arow][aq * 4 + 2] = av.z;
            As[arow][aq * 4 + 3] = av.w;
        }
        Bs4[brow][bq]      = *reinterpret_cast<const float4*>(&W[(size_t)(k0 + brow) * HID + n0 + bq * 4]);
        Bs4[brow + 16][bq] = *reinterpret_cast<const float4*>(&W[(size_t)(k0 + brow + 16) * HID + n0 + bq * 4]);
        __syncthreads();
#pragma unroll
        for (int kk = 0; kk < 32; kk++) {
            float4 bb = Bs4[kk][tx];
            float a = As[ty][kk];
            acc[0] += a * bb.x; acc[1] += a * bb.y; acc[2] += a * bb.z; acc[3] += a * bb.w;
        }
        __syncthreads();
    }

    float4 bv = *reinterpret_cast<const float4*>(&bias[n0 + tx * 4]);
    float v[4];
    v[0] = acc[0] + bv.x; v[1] = acc[1] + bv.y; v[2] = acc[2] + bv.z; v[3] = acc[3] + bv.w;

    *reinterpret_cast<float4*>(&C[(size_t)(m0 + ty) * HID + n0 + tx * 4]) =
        make_float4(v[0], v[1], v[2], v[3]);

#pragma unroll
    for (int j = 0; j < 4; j++) {
        red_s[ty][tx * 4 + j] = v[j];
        red_q[ty][tx * 4 + j] = v[j] * v[j];
    }
    __syncthreads();
    if (t < 64) {
        float S = 0.f, Q = 0.f;
#pragma unroll
        for (int g = 0; g < 16; g++) { S += red_s[g][t]; Q += red_q[g][t]; }
        atomicAdd(&gsum[n0 + t],   S);
        atomicAdd(&gsumsq[n0 + t], Q);
    }
}

// ---------------------------------------------------------------------------
// 3) GEMM2: vn = relu(h1*scale + shift) @ W2 + b2.
//    Prologue computes scale/shift per channel from gsum/gsumsq in smem.
// ---------------------------------------------------------------------------
__global__ __launch_bounds__(256) void gemm2_kernel(
    const float* __restrict__ A, const float* __restrict__ W,
    const float* __restrict__ bias, const float* __restrict__ gamma,
    const float* __restrict__ beta, const float* __restrict__ gsum,
    const float* __restrict__ gsumsq, float* __restrict__ C)
{
    __shared__ float  As[16][33];
    __shared__ float4 Bs4[32][16];
    __shared__ float  scale_s[HID];
    __shared__ float  shift_s[HID];

    int t  = threadIdx.x;
    {
        float mean = gsum[t] * (1.f / NB);
        float var  = gsumsq[t] * (1.f / NB) - mean * mean;
        float sc   = gamma[t] * rsqrtf(var + EPS);
        scale_s[t] = sc;
        shift_s[t] = beta[t] - mean * sc;
    }
    __syncthreads();

    int tx = t & 15, ty = t >> 4;
    int m0 = blockIdx.y * 16;
    int n0 = blockIdx.x * 64;

    float acc[4] = {0.f, 0.f, 0.f, 0.f};

    int brow = t >> 4, bq = t & 15;

    for (int k0 = 0; k0 < HID; k0 += 32) {
        if (t < 128) {
            int arow = t >> 3, aq = t & 7;
            int kc = k0 + aq * 4;
            float4 av = *reinterpret_cast<const float4*>(&A[(size_t)(m0 + arow) * HID + kc]);
            As[arow][aq * 4 + 0] = fmaxf(av.x * scale_s[kc + 0] + shift_s[kc + 0], 0.f);
            As[arow][aq * 4 + 1] = fmaxf(av.y * scale_s[kc + 1] + shift_s[kc + 1], 0.f);
            As[arow][aq * 4 + 2] = fmaxf(av.z * scale_s[kc + 2] + shift_s[kc + 2], 0.f);
            As[arow][aq * 4 + 3] = fmaxf(av.w * scale_s[kc + 3] + shift_s[kc + 3], 0.f);
        }
        Bs4[brow][bq]      = *reinterpret_cast<const float4*>(&W[(size_t)(k0 + brow) * HID + n0 + bq * 4]);
        Bs4[brow + 16][bq] = *reinterpret_cast<const float4*>(&W[(size_t)(k0 + brow + 16) * HID + n0 + bq * 4]);
        __syncthreads();
#pragma unroll
        for (int kk = 0; kk < 32; kk++) {
            float4 bb = Bs4[kk][tx];
            float a = As[ty][kk];
            acc[0] += a * bb.x; acc[1] += a * bb.y; acc[2] += a * bb.z; acc[3] += a * bb.w;
        }
        __syncthreads();
    }

    float4 bv = *reinterpret_cast<const float4*>(&bias[n0 + tx * 4]);
    float4 o;
    o.x = acc[0] + bv.x; o.y = acc[1] + bv.y;
    o.z = acc[2] + bv.z; o.w = acc[3] + bv.w;
    *reinterpret_cast<float4*>(&C[(size_t)(m0 + ty) * HID + n0 + tx * 4]) = o;
}

// ---------------------------------------------------------------------------
// 4) gather broadcast-add: x_out = x + vn[batch_idx].   (unchanged: 85% DRAM)
// ---------------------------------------------------------------------------
__global__ __launch_bounds__(256) void gather_kernel(
    const float* __restrict__ x, const int* __restrict__ bidx,
    const float* __restrict__ vn, float* __restrict__ out, unsigned total4)
{
    const float4* x4  = reinterpret_cast<const float4*>(x);
    const float4* vn4 = reinterpret_cast<const float4*>(vn);
    float4*       o4  = reinterpret_cast<float4*>(out);

    unsigned base = blockIdx.x * 1024u + threadIdx.x;

    if (base + 768u < total4) {
        unsigned i0 = base, i1 = base + 256u, i2 = base + 512u, i3 = base + 768u;

        int g0 = __ldg(&bidx[i0 >> 6]);
        int g1 = __ldg(&bidx[i1 >> 6]);
        int g2 = __ldg(&bidx[i2 >> 6]);
        int g3 = __ldg(&bidx[i3 >> 6]);

        float4 a0 = __ldcs(&x4[i0]);
        float4 a1 = __ldcs(&x4[i1]);
        float4 a2 = __ldcs(&x4[i2]);
        float4 a3 = __ldcs(&x4[i3]);

        float4 v0 = vn4[(unsigned)g0 * H4 + (i0 & 63u)];
        float4 v1 = vn4[(unsigned)g1 * H4 + (i1 & 63u)];
        float4 v2 = vn4[(unsigned)g2 * H4 + (i2 & 63u)];
        float4 v3 = vn4[(unsigned)g3 * H4 + (i3 & 63u)];

        float4 o;
        o.x = a0.x + v0.x; o.y = a0.y + v0.y; o.z = a0.z + v0.z; o.w = a0.w + v0.w;
        __stcs(&o4[i0], o);
        o.x = a1.x + v1.x; o.y = a1.y + v1.y; o.z = a1.z + v1.z; o.w = a1.w + v1.w;
        __stcs(&o4[i1], o);
        o.x = a2.x + v2.x; o.y = a2.y + v2.y; o.z = a2.z + v2.z; o.w = a2.w + v2.w;
        __stcs(&o4[i2], o);
        o.x = a3.x + v3.x; o.y = a3.y + v3.y; o.z = a3.z + v3.z; o.w = a3.w + v3.w;
        __stcs(&o4[i3], o);
    } else {
#pragma unroll
        for (int j = 0; j < 4; j++) {
            unsigned i = base + (unsigned)j * 256u;
            if (i < total4) {
                int g = __ldg(&bidx[i >> 6]);
                float4 a = __ldcs(&x4[i]);
                float4 v = vn4[(unsigned)g * H4 + (i & 63u)];
                float4 o;
                o.x = a.x + v.x; o.y = a.y + v.y; o.z = a.z + v.z; o.w = a.w + v.w;
                __stcs(&o4[i], o);
            }
        }
    }
}

// ---------------------------------------------------------------------------
extern "C" void kernel_launch(void* const* d_in, const int* in_sizes, int n_in,
                              void* d_out, int out_size)
{
    const float* x     = (const float*)d_in[0];
    const int*   bidx  = (const int*)  d_in[1];
    const float* vnode = (const float*)d_in[2];
    const float* W1    = (const float*)d_in[3];
    const float* b1    = (const float*)d_in[4];
    const float* gamma = (const float*)d_in[5];
    const float* beta  = (const float*)d_in[6];
    const float* W2    = (const float*)d_in[7];
    const float* b2    = (const float*)d_in[8];

    int n = in_sizes[0] / HID;             // number of nodes

    float* out   = (float*)d_out;          // x_out: [n, H]
    float* vnout = out + (size_t)n * HID;  // vn: [B, H]

    float* hpool; cudaGetSymbolAddress((void**)&hpool, g_hpool);
    float* h1;    cudaGetSymbolAddress((void**)&h1,    g_h1);
    float* gsum;  cudaGetSymbolAddress((void**)&gsum,  g_sum);
    float* gsq;   cudaGetSymbolAddress((void**)&gsq,   g_sumsq);
    int*   seg;   cudaGetSymbolAddress((void**)&seg,   g_segstart);

    bounds_kernel<<<(NB + 1 + 255) / 256, 256>>>(bidx, seg, gsum, gsq, n);

    pool_kernel<<<NB * 2, 256>>>(x, seg, vnode, hpool);

    dim3 ggrid(HID / 64, NB / 16);         // (4, 64) = 256 blocks
    gemm1_kernel<<<ggrid, 256>>>(hpool, W1, b1, h1, gsum, gsq);
    gemm2_kernel<<<ggrid, 256>>>(h1, W2, b2, gamma, beta, gsum, gsq, vnout);

    unsigned total4 = (unsigned)n * H4;
    int blocks = (int)((total4 + 1023u) / 1024u);
    gather_kernel<<<blocks, 256>>>(x, bidx, vnout, out, total4);
}

// round 6
// speedup vs baseline: 1.0362x; 1.0362x over previous
#include <cuda_runtime.h>
#include <cstdint>

#define HID 256
#define H4  64            // HID/4 float4 per row
#define NB  1024          // number of graphs
#define EPS 1e-5f

// scratch (allocation-free rule: static __device__ globals)
__device__ float g_hpool[NB * HID];
__device__ float g_h1[NB * HID];
__device__ float g_sum[HID];
__device__ float g_sumsq[HID];

// ---------------------------------------------------------------------------
// 1) segment-sum pooling (+ virtual_node). batch_idx SORTED -> binary search.
//    2 blocks per graph (column halves). 256 thr = 32 float4 cols x 8 rowgrps.
//    Block 0 also zeroes the BN stat accumulators. (round-3 body)
// ---------------------------------------------------------------------------
__global__ __launch_bounds__(256) void pool_kernel(
    const float* __restrict__ x, const int* __restrict__ bidx,
    const float* __restrict__ vnode, float* __restrict__ hpool,
    float* __restrict__ gsum, float* __restrict__ gsumsq, int n)
{
    int t = threadIdx.x;
    if (blockIdx.x == 0) { gsum[t] = 0.f; gsumsq[t] = 0.f; }

    int b    = blockIdx.x >> 1;
    int half = blockIdx.x & 1;

    int lo = 0, hi = n;
    while (lo < hi) { int m = (lo + hi) >> 1; if (bidx[m] < b) lo = m + 1; else hi = m; }
    int seg_lo = lo;
    hi = n;
    while (lo < hi) { int m = (lo + hi) >> 1; if (bidx[m] < b + 1) lo = m + 1; else hi = m; }
    int seg_hi = lo;

    int c4 = (half << 5) + (t & 31);   // global float4 column 0..63
    int rg = t >> 5;                   // row group 0..7

    const float4* x4 = reinterpret_cast<const float4*>(x);
    float4 acc = make_float4(0.f, 0.f, 0.f, 0.f);
#pragma unroll 4
    for (int r = seg_lo + rg; r < seg_hi; r += 8) {
        float4 v = __ldcs(&x4[(size_t)r * H4 + c4]);
        acc.x += v.x; acc.y += v.y; acc.z += v.z; acc.w += v.w;
    }

    __shared__ float4 sm[256];
    sm[t] = acc;
    __syncthreads();
    if (t < 32) {
        float4 o = reinterpret_cast<const float4*>(vnode)[b * H4 + c4];
#pragma unroll
        for (int g = 0; g < 8; g++) {
            float4 v = sm[g * 32 + t];
            o.x += v.x; o.y += v.y; o.z += v.z; o.w += v.w;
        }
        reinterpret_cast<float4*>(hpool)[b * H4 + c4] = o;
    }
}

// ---------------------------------------------------------------------------
// 2) GEMM1: h1 = hpool @ W1 + b1, fused BN-stat partial sums (atomicAdd).
//    32x64 tile, K-chunk 32, DOUBLE-BUFFERED smem (prefetch hides LDG latency).
// ---------------------------------------------------------------------------
__global__ __launch_bounds__(256) void gemm1_kernel(
    const float* __restrict__ A, const float* __restrict__ W,
    const float* __restrict__ bias, float* __restrict__ C,
    float* __restrict__ gsum, float* __restrict__ gsumsq)
{
    __shared__ float  As[2][32][33];
    __shared__ float4 Bs4[2][32][16];
    __shared__ float  red_s[16][64];
    __shared__ float  red_q[16][64];

    int t  = threadIdx.x;
    int tx = t & 15, ty = t >> 4;
    int m0 = blockIdx.y * 32;
    int n0 = blockIdx.x * 64;

    int arow = t >> 3, aq = t & 7;     // A: 32 rows x 8 float4
    int brow = t >> 4, bq = t & 15;    // B: 16 rows x 16 float4 (x2)

    const float4* Ar = reinterpret_cast<const float4*>(&A[(size_t)(m0 + arow) * HID]);

    // prologue: chunk 0
    float4 a_r  = Ar[aq];
    float4 b_r0 = *reinterpret_cast<const float4*>(&W[(size_t)brow * HID + n0 + bq * 4]);
    float4 b_r1 = *reinterpret_cast<const float4*>(&W[(size_t)(brow + 16) * HID + n0 + bq * 4]);
    As[0][arow][aq * 4 + 0] = a_r.x;
    As[0][arow][aq * 4 + 1] = a_r.y;
    As[0][arow][aq * 4 + 2] = a_r.z;
    As[0][arow][aq * 4 + 3] = a_r.w;
    Bs4[0][brow][bq]      = b_r0;
    Bs4[0][brow + 16][bq] = b_r1;
    __syncthreads();

    float acc[2][4];
#pragma unroll
    for (int i = 0; i < 2; i++)
#pragma unroll
        for (int j = 0; j < 4; j++) acc[i][j] = 0.f;

#pragma unroll
    for (int it = 0; it < 8; it++) {
        int cur = it & 1;
        if (it < 7) {
            int k1 = (it + 1) * 32;
            a_r  = Ar[(it + 1) * 8 + aq];
            b_r0 = *reinterpret_cast<const float4*>(&W[(size_t)(k1 + brow) * HID + n0 + bq * 4]);
            b_r1 = *reinterpret_cast<const float4*>(&W[(size_t)(k1 + brow + 16) * HID + n0 + bq * 4]);
        }
#pragma unroll
        for (int kk = 0; kk < 32; kk++) {
            float4 bb = Bs4[cur][kk][tx];
            float a0 = As[cur][ty * 2 + 0][kk];
            float a1 = As[cur][ty * 2 + 1][kk];
            acc[0][0] += a0 * bb.x; acc[0][1] += a0 * bb.y; acc[0][2] += a0 * bb.z; acc[0][3] += a0 * bb.w;
            acc[1][0] += a1 * bb.x; acc[1][1] += a1 * bb.y; acc[1][2] += a1 * bb.z; acc[1][3] += a1 * bb.w;
        }
        if (it < 7) {
            int nxt = cur ^ 1;
            As[nxt][arow][aq * 4 + 0] = a_r.x;
            As[nxt][arow][aq * 4 + 1] = a_r.y;
            As[nxt][arow][aq * 4 + 2] = a_r.z;
            As[nxt][arow][aq * 4 + 3] = a_r.w;
            Bs4[nxt][brow][bq]      = b_r0;
            Bs4[nxt][brow + 16][bq] = b_r1;
        }
        __syncthreads();
    }

    float4 bv = *reinterpret_cast<const float4*>(&bias[n0 + tx * 4]);
    float v0[4], v1[4];
    v0[0] = acc[0][0] + bv.x; v0[1] = acc[0][1] + bv.y; v0[2] = acc[0][2] + bv.z; v0[3] = acc[0][3] + bv.w;
    v1[0] = acc[1][0] + bv.x; v1[1] = acc[1][1] + bv.y; v1[2] = acc[1][2] + bv.z; v1[3] = acc[1][3] + bv.w;

    *reinterpret_cast<float4*>(&C[(size_t)(m0 + ty * 2 + 0) * HID + n0 + tx * 4]) =
        make_float4(v0[0], v0[1], v0[2], v0[3]);
    *reinterpret_cast<float4*>(&C[(size_t)(m0 + ty * 2 + 1) * HID + n0 + tx * 4]) =
        make_float4(v1[0], v1[1], v1[2], v1[3]);

#pragma unroll
    for (int j = 0; j < 4; j++) {
        red_s[ty][tx * 4 + j] = v0[j] + v1[j];
        red_q[ty][tx * 4 + j] = v0[j] * v0[j] + v1[j] * v1[j];
    }
    __syncthreads();
    if (t < 64) {
        float S = 0.f, Q = 0.f;
#pragma unroll
        for (int g = 0; g < 16; g++) { S += red_s[g][t]; Q += red_q[g][t]; }
        atomicAdd(&gsum[n0 + t],   S);
        atomicAdd(&gsumsq[n0 + t], Q);
    }
}

// ---------------------------------------------------------------------------
// 3) GEMM2: vn = relu(h1*scale + shift) @ W2 + b2. Double-buffered; BN+ReLU
//    applied at A smem-store time; scale/shift from gsum/gsumsq in prologue.
// ---------------------------------------------------------------------------
__global__ __launch_bounds__(256) void gemm2_kernel(
    const float* __restrict__ A, const float* __restrict__ W,
    const float* __restrict__ bias, const float* __restrict__ gamma,
    const float* __restrict__ beta, const float* __restrict__ gsum,
    const float* __restrict__ gsumsq, float* __restrict__ C)
{
    __shared__ float  As[2][32][33];
    __shared__ float4 Bs4[2][32][16];
    __shared__ float  scale_s[HID];
    __shared__ float  shift_s[HID];

    int t  = threadIdx.x;
    {
        float mean = gsum[t] * (1.f / NB);
        float var  = gsumsq[t] * (1.f / NB) - mean * mean;
        float sc   = gamma[t] * rsqrtf(var + EPS);
        scale_s[t] = sc;
        shift_s[t] = beta[t] - mean * sc;
    }
    __syncthreads();

    int tx = t & 15, ty = t >> 4;
    int m0 = blockIdx.y * 32;
    int n0 = blockIdx.x * 64;

    int arow = t >> 3, aq = t & 7;
    int brow = t >> 4, bq = t & 15;

    const float4* Ar = reinterpret_cast<const float4*>(&A[(size_t)(m0 + arow) * HID]);

    // prologue: chunk 0
    float4 a_r  = Ar[aq];
    float4 b_r0 = *reinterpret_cast<const float4*>(&W[(size_t)brow * HID + n0 + bq * 4]);
    float4 b_r1 = *reinterpret_cast<const float4*>(&W[(size_t)(brow + 16) * HID + n0 + bq * 4]);
    {
        int kc = aq * 4;
        As[0][arow][kc - 0 + 0] = fmaxf(a_r.x * scale_s[kc + 0] + shift_s[kc + 0], 0.f);
        As[0][arow][kc + 1]     = fmaxf(a_r.y * scale_s[kc + 1] + shift_s[kc + 1], 0.f);
        As[0][arow][kc + 2]     = fmaxf(a_r.z * scale_s[kc + 2] + shift_s[kc + 2], 0.f);
        As[0][arow][kc + 3]     = fmaxf(a_r.w * scale_s[kc + 3] + shift_s[kc + 3], 0.f);
    }
    Bs4[0][brow][bq]      = b_r0;
    Bs4[0][brow + 16][bq] = b_r1;
    __syncthreads();

    float acc[2][4];
#pragma unroll
    for (int i = 0; i < 2; i++)
#pragma unroll
        for (int j = 0; j < 4; j++) acc[i][j] = 0.f;

#pragma unroll
    for (int it = 0; it < 8; it++) {
        int cur = it & 1;
        if (it < 7) {
            int k1 = (it + 1) * 32;
            a_r  = Ar[(it + 1) * 8 + aq];
            b_r0 = *reinterpret_cast<const float4*>(&W[(size_t)(k1 + brow) * HID + n0 + bq * 4]);
            b_r1 = *reinterpret_cast<const float4*>(&W[(size_t)(k1 + brow + 16) * HID + n0 + bq * 4]);
        }
#pragma unroll
        for (int kk = 0; kk < 32; kk++) {
            float4 bb = Bs4[cur][kk][tx];
            float a0 = As[cur][ty * 2 + 0][kk];
            float a1 = As[cur][ty * 2 + 1][kk];
            acc[0][0] += a0 * bb.x; acc[0][1] += a0 * bb.y; acc[0][2] += a0 * bb.z; acc[0][3] += a0 * bb.w;
            acc[1][0] += a1 * bb.x; acc[1][1] += a1 * bb.y; acc[1][2] += a1 * bb.z; acc[1][3] += a1 * bb.w;
        }
        if (it < 7) {
            int nxt = cur ^ 1;
            int kc  = (it + 1) * 32 + aq * 4;
            int sc0 = aq * 4;
            As[nxt][arow][sc0 + 0] = fmaxf(a_r.x * scale_s[kc + 0] + shift_s[kc + 0], 0.f);
            As[nxt][arow][sc0 + 1] = fmaxf(a_r.y * scale_s[kc + 1] + shift_s[kc + 1], 0.f);
            As[nxt][arow][sc0 + 2] = fmaxf(a_r.z * scale_s[kc + 2] + shift_s[kc + 2], 0.f);
            As[nxt][arow][sc0 + 3] = fmaxf(a_r.w * scale_s[kc + 3] + shift_s[kc + 3], 0.f);
            Bs4[nxt][brow][bq]      = b_r0;
            Bs4[nxt][brow + 16][bq] = b_r1;
        }
        __syncthreads();
    }

    float4 bv = *reinterpret_cast<const float4*>(&bias[n0 + tx * 4]);
#pragma unroll
    for (int i = 0; i < 2; i++) {
        float4 o;
        o.x = acc[i][0] + bv.x; o.y = acc[i][1] + bv.y;
        o.z = acc[i][2] + bv.z; o.w = acc[i][3] + bv.w;
        *reinterpret_cast<float4*>(&C[(size_t)(m0 + ty * 2 + i) * HID + n0 + tx * 4]) = o;
    }
}

// ---------------------------------------------------------------------------
// 4) gather broadcast-add: x_out = x + vn[batch_idx].   (unchanged: 85% DRAM)
// ---------------------------------------------------------------------------
__global__ __launch_bounds__(256) void gather_kernel(
    const float* __restrict__ x, const int* __restrict__ bidx,
    const float* __restrict__ vn, float* __restrict__ out, unsigned total4)
{
    const float4* x4  = reinterpret_cast<const float4*>(x);
    const float4* vn4 = reinterpret_cast<const float4*>(vn);
    float4*       o4  = reinterpret_cast<float4*>(out);

    unsigned base = blockIdx.x * 1024u + threadIdx.x;

    if (base + 768u < total4) {
        unsigned i0 = base, i1 = base + 256u, i2 = base + 512u, i3 = base + 768u;

        int g0 = __ldg(&bidx[i0 >> 6]);
        int g1 = __ldg(&bidx[i1 >> 6]);
        int g2 = __ldg(&bidx[i2 >> 6]);
        int g3 = __ldg(&bidx[i3 >> 6]);

        float4 a0 = __ldcs(&x4[i0]);
        float4 a1 = __ldcs(&x4[i1]);
        float4 a2 = __ldcs(&x4[i2]);
        float4 a3 = __ldcs(&x4[i3]);

        float4 v0 = vn4[(unsigned)g0 * H4 + (i0 & 63u)];
        float4 v1 = vn4[(unsigned)g1 * H4 + (i1 & 63u)];
        float4 v2 = vn4[(unsigned)g2 * H4 + (i2 & 63u)];
        float4 v3 = vn4[(unsigned)g3 * H4 + (i3 & 63u)];

        float4 o;
        o.x = a0.x + v0.x; o.y = a0.y + v0.y; o.z = a0.z + v0.z; o.w = a0.w + v0.w;
        __stcs(&o4[i0], o);
        o.x = a1.x + v1.x; o.y = a1.y + v1.y; o.z = a1.z + v1.z; o.w = a1.w + v1.w;
        __stcs(&o4[i1], o);
        o.x = a2.x + v2.x; o.y = a2.y + v2.y; o.z = a2.z + v2.z; o.w = a2.w + v2.w;
        __stcs(&o4[i2], o);
        o.x = a3.x + v3.x; o.y = a3.y + v3.y; o.z = a3.z + v3.z; o.w = a3.w + v3.w;
        __stcs(&o4[i3], o);
    } else {
#pragma unroll
        for (int j = 0; j < 4; j++) {
            unsigned i = base + (unsigned)j * 256u;
            if (i < total4) {
                int g = __ldg(&bidx[i >> 6]);
                float4 a = __ldcs(&x4[i]);
                float4 v = vn4[(unsigned)g * H4 + (i & 63u)];
                float4 o;
                o.x = a.x + v.x; o.y = a.y + v.y; o.z = a.z + v.z; o.w = a.w + v.w;
                __stcs(&o4[i], o);
            }
        }
    }
}

// ---------------------------------------------------------------------------
extern "C" void kernel_launch(void* const* d_in, const int* in_sizes, int n_in,
                              void* d_out, int out_size)
{
    const float* x     = (const float*)d_in[0];
    const int*   bidx  = (const int*)  d_in[1];
    const float* vnode = (const float*)d_in[2];
    const float* W1    = (const float*)d_in[3];
    const float* b1    = (const float*)d_in[4];
    const float* gamma = (const float*)d_in[5];
    const float* beta  = (const float*)d_in[6];
    const float* W2    = (const float*)d_in[7];
    const float* b2    = (const float*)d_in[8];

    int n = in_sizes[0] / HID;             // number of nodes

    float* out   = (float*)d_out;          // x_out: [n, H]
    float* vnout = out + (size_t)n * HID;  // vn: [B, H]

    float* hpool; cudaGetSymbolAddress((void**)&hpool, g_hpool);
    float* h1;    cudaGetSymbolAddress((void**)&h1,    g_h1);
    float* gsum;  cudaGetSymbolAddress((void**)&gsum,  g_sum);
    float* gsq;   cudaGetSymbolAddress((void**)&gsq,   g_sumsq);

    pool_kernel<<<NB * 2, 256>>>(x, bidx, vnode, hpool, gsum, gsq, n);

    dim3 ggrid(HID / 64, NB / 32);         // (4, 32) = 128 blocks
    gemm1_kernel<<<ggrid, 256>>>(hpool, W1, b1, h1, gsum, gsq);
    gemm2_kernel<<<ggrid, 256>>>(h1, W2, b2, gamma, beta, gsum, gsq, vnout);

    unsigned total4 = (unsigned)n * H4;
    int blocks = (int)((total4 + 1023u) / 1024u);
    gather_kernel<<<blocks, 256>>>(x, bidx, vnout, out, total4);
}